// round 17
// baseline (speedup 1.0000x reference)
#include <cuda_runtime.h>
#include <cuda_bf16.h>
#include <cuda_fp16.h>
#include <cstdint>

#define BNUM 2
#define SLEN 2048
#define DDIM 1024
#define HNUM 16
#define DKQ  64
#define WPD  36     // word pitch for 32-data-word rows (+4 pad): banks 4*lr+lc, conflict-free

__device__ uint32_t g_wt16[3][DDIM*DDIM/2];          // packed fp16 Wt[n][k]
__device__ uint32_t g_af16[3][BNUM*SLEN*DDIM/2];     // packed fp16 inputs
// attention-ready tiles (all packed fp16x2)
__device__ uint32_t g_qf16[BNUM*HNUM*SLEN*DKQ/2];    // Q*0.125, [bh][s][dk/2]
__device__ uint32_t g_kf16[BNUM*HNUM*SLEN*DKQ/2];    // K,       [bh][s][dk/2]
__device__ uint32_t g_vt2 [BNUM*HNUM*DKQ*SLEN/2];    // V,       [bh][d][s_pair]

// ---------------- helpers ----------------
__device__ __forceinline__ uint32_t smem_u32(const void* p) {
    uint32_t a;
    asm("{ .reg .u64 t; cvta.to.shared.u64 t, %1; cvt.u32.u64 %0, t; }"
        : "=r"(a) : "l"(p));
    return a;
}
__device__ __forceinline__ void cp16(uint32_t dst, const void* src) {
    asm volatile("cp.async.cg.shared.global [%0], [%1], 16;"
                 :: "r"(dst), "l"(src));
}
#define CP_COMMIT() asm volatile("cp.async.commit_group;" ::: "memory")
#define CP_WAIT0()  asm volatile("cp.async.wait_group 0;" ::: "memory")

__device__ __forceinline__ void mma_fp16(
    float& d0, float& d1, float& d2, float& d3,
    uint32_t a0, uint32_t a1, uint32_t a2, uint32_t a3,
    uint32_t b0, uint32_t b1)
{
    asm volatile(
        "mma.sync.aligned.m16n8k16.row.col.f32.f16.f16.f32 "
        "{%0,%1,%2,%3}, {%4,%5,%6,%7}, {%8,%9}, {%0,%1,%2,%3};"
        : "+f"(d0), "+f"(d1), "+f"(d2), "+f"(d3)
        : "r"(a0), "r"(a1), "r"(a2), "r"(a3), "r"(b0), "r"(b1));
}
__device__ __forceinline__ uint32_t pack_h2(float a, float b) {
    __half2 h = __floats2half2_rn(a, b);
    return *(uint32_t*)&h;
}

// ---------------- pre-pass: inputs fp32 -> packed fp16 (3 arrays via y) ----------------
__global__ __launch_bounds__(256) void cvt_f16_kernel(
    const float4* __restrict__ q, const float4* __restrict__ k,
    const float4* __restrict__ v,
    uint2* __restrict__ oq, uint2* __restrict__ ok, uint2* __restrict__ ov, int n4)
{
    int i = blockIdx.x * blockDim.x + threadIdx.x;
    if (i >= n4) return;
    const float4* in = (blockIdx.y == 0) ? q : (blockIdx.y == 1) ? k : v;
    uint2* out       = (blockIdx.y == 0) ? oq : (blockIdx.y == 1) ? ok : ov;
    float4 x = in[i];
    uint2 o = { pack_h2(x.x, x.y), pack_h2(x.z, x.w) };
    out[i] = o;
}

// ---------------- fused weight transpose + fp16 pack, 3 weights via z ----------------
__global__ __launch_bounds__(256) void transpose_pack_kernel(
    const float* __restrict__ w0, const float* __restrict__ w1, const float* __restrict__ w2,
    uint32_t* __restrict__ o0, uint32_t* __restrict__ o1, uint32_t* __restrict__ o2)
{
    __shared__ float t[32][33];
    const float* in = (blockIdx.z == 0) ? w0 : (blockIdx.z == 1) ? w1 : w2;
    uint32_t* out   = (blockIdx.z == 0) ? o0 : (blockIdx.z == 1) ? o1 : o2;
    const int tx = threadIdx.x, ty = threadIdx.y;
    int x = blockIdx.x*32 + tx;
    int y0 = blockIdx.y*32;
#pragma unroll
    for (int j = 0; j < 32; j += 8)
        t[ty + j][tx] = in[(size_t)(y0 + ty + j)*DDIM + x];
    __syncthreads();
    const int tid = ty * 32 + tx;
#pragma unroll
    for (int i = 0; i < 2; i++) {
        int idx = tid + i * 256;          // 0..511 = 32 rows x 16 words
        int row = idx >> 4, wrd = idx & 15;
        uint32_t w = pack_h2(t[2*wrd][row], t[2*wrd + 1][row]);
        out[(size_t)(blockIdx.x*32 + row)*(DDIM/2) + blockIdx.y*16 + wrd] = w;
    }
}

// ---------------- fp16 HMMA projection, K-chunk 64, single-sync pipeline ----------------
// z=0: Q -> scale 0.125, packed fp16 [bh][s][dk/2].
// z=1: K -> packed fp16 [bh][s][dk/2].
// z=2: V -> packed fp16x2 TRANSPOSED [bh][d][s_pair] (shuffle-paired in epilogue).
__global__ __launch_bounds__(256, 2) void proj_mma_kernel(
    const uint32_t* __restrict__ A0, const uint32_t* __restrict__ A1, const uint32_t* __restrict__ A2,
    const uint32_t* __restrict__ W0, const uint32_t* __restrict__ W1, const uint32_t* __restrict__ W2,
    const float* __restrict__ bias0, const float* __restrict__ bias1, const float* __restrict__ bias2,
    uint32_t* __restrict__ qf, uint32_t* __restrict__ kf,
    uint32_t* __restrict__ vt2)
{
    extern __shared__ uint32_t psm[];        // As[2][128][WPD] | Bs[2][128][WPD]
    uint32_t* As = psm;
    uint32_t* Bs = psm + 2*128*WPD;
    const uint32_t as_u = smem_u32(As);
    const uint32_t bs_u = smem_u32(Bs);

    const int z = blockIdx.z;
    const uint32_t* A  = (z == 0) ? A0 : (z == 1) ? A1 : A2;
    const uint32_t* Wt = (z == 0) ? W0 : (z == 1) ? W1 : W2;
    const float* bias  = (z == 0) ? bias0 : (z == 1) ? bias1 : bias2;

    const int tid  = threadIdx.x;
    const int wid  = tid >> 5;
    const int lane = tid & 31;
    const int lr   = lane >> 2;
    const int lc   = lane & 3;
    const int wm   = (wid >> 2) * 64;
    const int wn   = (wid & 3) * 32;
    const int col0 = blockIdx.x << 7;
    const int row0 = blockIdx.y << 7;

    const uint32_t* Abase = A  + (size_t)row0 * (DDIM/2);
    const uint32_t* Bbase = Wt + (size_t)col0 * (DDIM/2);

    auto issue = [&](int c, int s) {
#pragma unroll
        for (int it = 0; it < 4; it++) {
            int f = tid + it * 256;          // 0..1023 : 128 rows x 8 cp16
            int r = f >> 3;
            int o = (f & 7) * 16;            // byte offset within 128B row
            uint32_t d = (uint32_t)((s*128 + r) * (WPD*4)) + o;
            cp16(as_u + d, (const char*)(Abase + (size_t)r * (DDIM/2) + c*32) + o);
            cp16(bs_u + d, (const char*)(Bbase + (size_t)r * (DDIM/2) + c*32) + o);
        }
    };

    float acc[4][4][4];
#pragma unroll
    for (int mt = 0; mt < 4; mt++)
#pragma unroll
        for (int nt = 0; nt < 4; nt++)
#pragma unroll
            for (int i = 0; i < 4; i++) acc[mt][nt][i] = 0.f;

    issue(0, 0); CP_COMMIT();

    for (int c = 0; c < 16; c++) {           // 16 K-chunks of 64 fp16
        const int s = c & 1;
        CP_WAIT0();                           // my stage-s copies done
        __syncthreads();                      // all copies visible; all stage-s^1 readers done
        if (c < 15) { issue(c + 1, s ^ 1); CP_COMMIT(); }

        const uint32_t* Ast = As + s*128*WPD;
        const uint32_t* Bst = Bs + s*128*WPD;
#pragma unroll
        for (int ks = 0; ks < 4; ks++) {     // four k16 steps per 64-chunk
            const int k8 = ks * 8;
            uint32_t a[4][4];
#pragma unroll
            for (int mt = 0; mt < 4; mt++) {
                int r = wm + mt * 16 + lr;
                a[mt][0] = Ast[r*WPD + k8 + lc];
                a[mt][1] = Ast[(r+8)*WPD + k8 + lc];
                a[mt][2] = Ast[r*WPD + k8 + lc + 4];
                a[mt][3] = Ast[(r+8)*WPD + k8 + lc + 4];
            }
#pragma unroll
            for (int nt = 0; nt < 4; nt++) {
                int n = wn + nt * 8 + lr;
                uint32_t b0 = Bst[n*WPD + k8 + lc];
                uint32_t b1 = Bst[n*WPD + k8 + lc + 4];
#pragma unroll
                for (int mt = 0; mt < 4; mt++)
                    mma_fp16(acc[mt][nt][0], acc[mt][nt][1],
                             acc[mt][nt][2], acc[mt][nt][3],
                             a[mt][0], a[mt][1], a[mt][2], a[mt][3], b0, b1);
            }
        }
    }

    // Epilogue: z<2 -> packed fp16 [bh][s][dk/2]; z==2 -> fp16x2 transposed.
    uint32_t* opk = (z == 0) ? qf : kf;
#pragma unroll
    for (int mt = 0; mt < 4; mt++) {
#pragma unroll
        for (int nt = 0; nt < 4; nt++) {
            int col = col0 + wn + nt * 8 + 2 * lc;
            float2 bb = *(const float2*)(bias + col);
            int head = col >> 6;
            int dk   = col & 63;
#pragma unroll
            for (int h = 0; h < 2; h++) {
                int row = row0 + wm + mt * 16 + lr + h * 8;
                int bi  = row >> 11;
                int si  = row & (SLEN - 1);
                float vx = acc[mt][nt][2*h + 0] + bb.x;
                float vy = acc[mt][nt][2*h + 1] + bb.y;
                if (z == 2) {
                    float px = __shfl_xor_sync(0xffffffffu, vx, 4);
                    float py = __shfl_xor_sync(0xffffffffu, vy, 4);
                    if (!(lane & 4)) {
                        size_t base = ((size_t)(bi * HNUM + head) * DKQ + dk) * (SLEN/2);
                        vt2[base + (si >> 1)]            = pack_h2(vx, px);
                        vt2[base + (SLEN/2) + (si >> 1)] = pack_h2(vy, py);
                    }
                } else {
                    if (z == 0) { vx *= 0.125f; vy *= 0.125f; }
                    size_t wi = ((size_t)(bi * HNUM + head) * SLEN + si) * 32 + (dk >> 1);
                    opk[wi] = pack_h2(vx, vy);
                }
            }
        }
    }
}

// ---------------- cp.async flash attention: Q direct from GMEM, single-sync ----------------
// Smem word offsets: stage s: Kf s*4608, Vt s*4608+2304. Total 9216 words (36864 B).
__global__ __launch_bounds__(128) void attn_mma_kernel(
    const uint32_t* __restrict__ Qf_g, const uint32_t* __restrict__ Kf_g,
    const uint32_t* __restrict__ Vt_g,  float* __restrict__ out)
{
    extern __shared__ uint32_t sm[];
    const uint32_t sm_u = smem_u32(sm);

    const int tid  = threadIdx.x;
    const int w    = tid >> 5;
    const int lane = tid & 31;
    const int lr   = lane >> 2;
    const int lc   = lane & 3;
    const int bh   = blockIdx.x;
    const int qt   = (gridDim.y - 1) - blockIdx.y;

    auto issue_kv = [&](int kt, int s) {
        const uint32_t* Kf_s = Kf_g + ((size_t)bh * SLEN + (size_t)kt * 64) * 32;
        const uint32_t* Vt_s = Vt_g + (size_t)bh * DKQ * (SLEN/2) + (size_t)kt * 32;
        const uint32_t kb = sm_u + (uint32_t)(s * 4608) * 4;
#pragma unroll
        for (int it = 0; it < 4; it++) {
            int f = tid + it * 128;          // 0..511 : 64 rows x 8 cp16
            int r = f >> 3;
            int o = (f & 7) * 16;
            uint32_t d = (uint32_t)(r * (WPD*4)) + o;
            cp16(kb + d,            (const char*)(Kf_s + (size_t)r * 32) + o);
            cp16(kb + 2304*4 + d,   (const char*)(Vt_s + (size_t)r * (SLEN/2)) + o);
        }
    };

    issue_kv(0, 0);
    CP_COMMIT();

    // Q fragments straight from global (kt-invariant, one-time).
    uint32_t qf_r[4][4];
    {
        const uint32_t* Qr0 = Qf_g + ((size_t)bh * SLEN + (size_t)qt * 64 + w*16 + lr) * 32;
        const uint32_t* Qr1 = Qr0 + 8 * 32;
#pragma unroll
        for (int ks = 0; ks < 4; ks++) {
            const int k8 = ks * 8;
            qf_r[ks][0] = Qr0[k8 + lc];
            qf_r[ks][1] = Qr1[k8 + lc];
            qf_r[ks][2] = Qr0[k8 + lc + 4];
            qf_r[ks][3] = Qr1[k8 + lc + 4];
        }
    }

    float accO[8][4];
#pragma unroll
    for (int nf = 0; nf < 8; nf++)
#pragma unroll
        for (int i = 0; i < 4; i++) accO[nf][i] = 0.f;
    float mrow[2] = { -1e30f, -1e30f };
    float lrow[2] = { 0.f, 0.f };

    uint32_t pw[2][8];                 // packed P words = PV A-fragments

    const int qrow0 = qt*64 + w*16 + lr;

    for (int kt = 0; kt <= qt; kt++) {
        const int s = kt & 1;
        CP_WAIT0();                          // my stage-s copies done
        __syncthreads();                     // all copies visible; stage-s^1 readers done
        if (kt < qt) { issue_kv(kt + 1, s ^ 1); CP_COMMIT(); }

        const uint32_t* Kfs = sm + s*4608;
        const uint32_t* Vts = Kfs + 2304;

        // ---- scores: fp16 QK^T ----
        float accS[8][4];
#pragma unroll
        for (int nf = 0; nf < 8; nf++)
#pragma unroll
            for (int i = 0; i < 4; i++) accS[nf][i] = 0.f;

#pragma unroll
        for (int ks = 0; ks < 4; ks++) {
            const int k8 = ks * 8;
#pragma unroll
            for (int nf = 0; nf < 8; nf++) {
                int nb = (nf*8 + lr) * WPD + k8 + lc;
                uint32_t b0 = Kfs[nb], b1 = Kfs[nb + 4];
                mma_fp16(accS[nf][0], accS[nf][1], accS[nf][2], accS[nf][3],
                         qf_r[ks][0], qf_r[ks][1], qf_r[ks][2], qf_r[ks][3], b0, b1);
            }
        }

        if (kt == qt) {
#pragma unroll
            for (int nf = 0; nf < 8; nf++) {
                int gc = kt*64 + nf*8 + 2*lc;
                if (gc     > qrow0)     accS[nf][0] = -1e30f;
                if (gc + 1 > qrow0)     accS[nf][1] = -1e30f;
                if (gc     > qrow0 + 8) accS[nf][2] = -1e30f;
                if (gc + 1 > qrow0 + 8) accS[nf][3] = -1e30f;
            }
        }

        // ---- online softmax; P kept in registers ----
#pragma unroll
        for (int h = 0; h < 2; h++) {
            const int i0 = 2*h, i1 = 2*h + 1;
            float rmax = accS[0][i0];
#pragma unroll
            for (int nf = 0; nf < 8; nf++) {
                rmax = fmaxf(rmax, accS[nf][i0]);
                rmax = fmaxf(rmax, accS[nf][i1]);
            }
            rmax = fmaxf(rmax, __shfl_xor_sync(0xffffffffu, rmax, 1));
            rmax = fmaxf(rmax, __shfl_xor_sync(0xffffffffu, rmax, 2));
            float mn   = fmaxf(mrow[h], rmax);
            float corr = __expf(mrow[h] - mn);
            mrow[h] = mn;
            float rsum = 0.f;
#pragma unroll
            for (int nf = 0; nf < 8; nf++) {
                float e0 = __expf(accS[nf][i0] - mn);
                float e1 = __expf(accS[nf][i1] - mn);
                __half2 hp = __floats2half2_rn(e0, e1);
                pw[h][nf] = *(uint32_t*)&hp;
                rsum += __low2float(hp) + __high2float(hp);
                accO[nf][i0] *= corr;
                accO[nf][i1] *= corr;
            }
            rsum += __shfl_xor_sync(0xffffffffu, rsum, 1);
            rsum += __shfl_xor_sync(0xffffffffu, rsum, 2);
            lrow[h] = lrow[h] * corr + rsum;
        }

        // ---- accO += P @ V (fp16); A-fragments ARE the pw registers ----
#pragma unroll
        for (int ks = 0; ks < 4; ks++) {
            const int k8 = ks * 8;
            uint32_t a0 = pw[0][2*ks];
            uint32_t a1 = pw[1][2*ks];
            uint32_t a2 = pw[0][2*ks + 1];
            uint32_t a3 = pw[1][2*ks + 1];
#pragma unroll
            for (int nf = 0; nf < 8; nf++) {
                int nb = (nf*8 + lr) * WPD + k8 + lc;
                uint32_t b0 = Vts[nb], b1 = Vts[nb + 4];
                mma_fp16(accO[nf][0], accO[nf][1], accO[nf][2], accO[nf][3],
                         a0, a1, a2, a3, b0, b1);
            }
        }
    }

    // ---- epilogue: out[B,S,D] ----
    const int b = bh >> 4, h = bh & 15;
    const float inv0 = 1.f / lrow[0];
    const float inv1 = 1.f / lrow[1];
    const int s0 = qt*64 + w*16 + lr;
    const int s1 = s0 + 8;
#pragma unroll
    for (int nf = 0; nf < 8; nf++) {
        int col = h*DKQ + nf*8 + 2*lc;
        float2 v0 = { accO[nf][0] * inv0, accO[nf][1] * inv0 };
        float2 v1 = { accO[nf][2] * inv1, accO[nf][3] * inv1 };
        *(float2*)(out + ((size_t)b * SLEN + s0) * DDIM + col) = v0;
        *(float2*)(out + ((size_t)b * SLEN + s1) * DDIM + col) = v1;
    }
}

extern "C" void kernel_launch(void* const* d_in, const int* in_sizes, int n_in,
                              void* d_out, int out_size) {
    const float* q  = (const float*)d_in[0];
    const float* k  = (const float*)d_in[1];
    const float* v  = (const float*)d_in[2];
    const float* Wq = (const float*)d_in[3];
    const float* bq = (const float*)d_in[4];
    const float* Wk = (const float*)d_in[5];
    const float* bk = (const float*)d_in[6];
    const float* Wv = (const float*)d_in[7];
    const float* bv = (const float*)d_in[8];
    float* out = (float*)d_out;

    uint32_t *gwt16, *gaf16, *gqf, *gkf, *gvt;
    cudaGetSymbolAddress((void**)&gwt16, g_wt16);
    cudaGetSymbolAddress((void**)&gaf16, g_af16);
    cudaGetSymbolAddress((void**)&gqf,   g_qf16);
    cudaGetSymbolAddress((void**)&gkf,   g_kf16);
    cudaGetSymbolAddress((void**)&gvt,   g_vt2);

    // Fused weight transpose + fp16 pack, one launch for all 3 weights.
    dim3 tgrid(DDIM/32, DDIM/32, 3), tblk(32, 8);
    transpose_pack_kernel<<<tgrid, tblk>>>(
        Wq, Wk, Wv,
        gwt16 + 0*DDIM*DDIM/2, gwt16 + 1*DDIM*DDIM/2, gwt16 + 2*DDIM*DDIM/2);

    // Inputs -> packed fp16, single launch.
    const size_t NA = (size_t)BNUM*SLEN*DDIM;
    const int na4 = (int)(NA/4);
    cvt_f16_kernel<<<dim3((na4+255)/256, 3), 256>>>(
        (const float4*)q, (const float4*)k, (const float4*)v,
        (uint2*)(gaf16 + 0*NA/2), (uint2*)(gaf16 + 1*NA/2), (uint2*)(gaf16 + 2*NA/2), na4);

    // Projections (K-chunk 64, single-sync pipeline); epilogue emits attn formats.
    const int proj_smem = 2 * 2 * 128 * WPD * 4;  // 73728
    cudaFuncSetAttribute(proj_mma_kernel,
        cudaFuncAttributeMaxDynamicSharedMemorySize, proj_smem);
    dim3 pgrid(DDIM/128, (BNUM*SLEN)/128, 3);
    proj_mma_kernel<<<pgrid, 256, proj_smem>>>(
        gaf16 + 0*NA/2, gaf16 + 1*NA/2, gaf16 + 2*NA/2,
        gwt16 + 0*DDIM*DDIM/2, gwt16 + 1*DDIM*DDIM/2, gwt16 + 2*DDIM*DDIM/2,
        bq, bk, bv,
        gqf, gkf, gvt);

    // Attention (Q direct from GMEM; smem 36864 B -> 6 CTAs/SM).
    const int attn_smem = 9216 * 4;               // 36864
    cudaFuncSetAttribute(attn_mma_kernel,
        cudaFuncAttributeMaxDynamicSharedMemorySize, attn_smem);
    attn_mma_kernel<<<dim3(BNUM*HNUM, SLEN/64), 128, attn_smem>>>(
        gqf, gkf, gvt, out);
}